// round 1
// baseline (speedup 1.0000x reference)
#include <cuda_runtime.h>

#define NNODES 100000
#define D 64
#define D4 16              // D/4
#define ALPHA 0.01f
#define BN_EPS 1e-5f

// -------- scratch (static device globals; no allocations allowed) --------
__device__ __align__(16) float g_deg[NNODES];
__device__ __align__(16) float g_dis[NNODES];
__device__ __align__(16) float g_h  [(size_t)NNODES * D];
__device__ __align__(16) float g_agg[(size_t)NNODES * D];
__device__ __align__(16) float g_sum[D];
__device__ __align__(16) float g_sumsq[D];

// -------- K0: reset per-replay state (deg=1 for self-loop, stats=0) ------
__global__ void k_init(int n) {
    int i = blockIdx.x * blockDim.x + threadIdx.x;
    if (i < n) g_deg[i] = 1.0f;
    if (i < D) { g_sum[i] = 0.0f; g_sumsq[i] = 0.0f; }
}

// -------- K1: weighted in-degree ----------------------------------------
__global__ void k_deg(const int* __restrict__ col, const float* __restrict__ w, int E) {
    int i = blockIdx.x * blockDim.x + threadIdx.x;
    if (i < E) atomicAdd(&g_deg[col[i]], w[i]);
}

// -------- K2: dis = deg^-1/2 (deg >= 1 always: self-loop weight 1) -------
__global__ void k_dis(int n) {
    int i = blockIdx.x * blockDim.x + threadIdx.x;
    if (i < n) g_dis[i] = rsqrtf(g_deg[i]);
}

// -------- K3: h = x @ W ; agg = h * dis^2 (self-loop contribution) -------
// block = (16,16): 16 nodes per block, each thread -> 4 output cols (float4)
__global__ void k_gemm(const float* __restrict__ x, const float* __restrict__ W, int n) {
    __shared__ float4 Ws[64 * D4];     // W[k][j] as float4 over j
    __shared__ float  xs[16 * 64];     // 16-node x tile
    const int tx = threadIdx.x;        // 0..15 -> col group
    const int ty = threadIdx.y;        // 0..15 -> node in tile
    const int tid = ty * 16 + tx;

    const float4* W4 = (const float4*)W;
#pragma unroll
    for (int i = 0; i < 4; i++) Ws[tid + i * 256] = W4[tid + i * 256];

    const int n0 = blockIdx.x * 16;
    ((float4*)xs)[tid] = ((const float4*)x)[n0 * D4 + tid];
    __syncthreads();

    float4 acc = make_float4(0.f, 0.f, 0.f, 0.f);
#pragma unroll
    for (int k = 0; k < 64; k++) {
        const float  a = xs[ty * 64 + k];
        const float4 w = Ws[k * D4 + tx];
        acc.x = fmaf(a, w.x, acc.x);
        acc.y = fmaf(a, w.y, acc.y);
        acc.z = fmaf(a, w.z, acc.z);
        acc.w = fmaf(a, w.w, acc.w);
    }
    const int node = n0 + ty;
    if (node < n) {
        float s = g_dis[node]; s *= s;           // dis[i]*1*dis[i] = 1/deg
        const int o = node * D4 + tx;
        ((float4*)g_h)[o]   = acc;
        ((float4*)g_agg)[o] = make_float4(acc.x * s, acc.y * s, acc.z * s, acc.w * s);
    }
}

// -------- K4: edge scatter: agg[c] += dis[r]*w*dis[c] * h[r] -------------
// 16 threads per edge, float4 gather + vectorized RED (no return) to L2.
__global__ void k_scatter(const int* __restrict__ row, const int* __restrict__ col,
                          const float* __restrict__ w, int E) {
    const long long gid = (long long)blockIdx.x * blockDim.x + threadIdx.x;
    const int e = (int)(gid >> 4);
    const int l = (int)(gid & 15);
    if (e >= E) return;
    const int r = row[e];
    const int c = col[e];
    const float nm = g_dis[r] * w[e] * g_dis[c];
    const float4 hv = ((const float4*)g_h)[r * D4 + l];
    float4* dst = ((float4*)g_agg) + c * D4 + l;
    asm volatile("red.global.add.v4.f32 [%0], {%1,%2,%3,%4};"
                 :: "l"(dst), "f"(hv.x * nm), "f"(hv.y * nm),
                    "f"(hv.z * nm), "f"(hv.w * nm)
                 : "memory");
}

// -------- K5: per-column sum / sumsq -------------------------------------
// block = 256 threads = 16 row-lanes x 16 col4-groups; grid-stride over rows.
__global__ void k_stats(int n) {
    __shared__ float4 ss [16][16];
    __shared__ float4 ss2[16][16];
    const int tid = threadIdx.x;
    const int c4 = tid & 15;
    const int rl = tid >> 4;
    float4 s  = make_float4(0.f, 0.f, 0.f, 0.f);
    float4 s2 = make_float4(0.f, 0.f, 0.f, 0.f);
    for (int r = blockIdx.x * 16 + rl; r < n; r += gridDim.x * 16) {
        const float4 v = ((const float4*)g_agg)[r * D4 + c4];
        s.x += v.x; s.y += v.y; s.z += v.z; s.w += v.w;
        s2.x = fmaf(v.x, v.x, s2.x);
        s2.y = fmaf(v.y, v.y, s2.y);
        s2.z = fmaf(v.z, v.z, s2.z);
        s2.w = fmaf(v.w, v.w, s2.w);
    }
    ss[rl][c4] = s; ss2[rl][c4] = s2;
    __syncthreads();
#pragma unroll
    for (int off = 8; off > 0; off >>= 1) {
        if (rl < off) {
            float4 a = ss[rl + off][c4], b = ss2[rl + off][c4];
            float4 u = ss[rl][c4],      v = ss2[rl][c4];
            u.x += a.x; u.y += a.y; u.z += a.z; u.w += a.w;
            v.x += b.x; v.y += b.y; v.z += b.z; v.w += b.w;
            ss[rl][c4] = u; ss2[rl][c4] = v;
        }
        __syncthreads();
    }
    if (rl == 0) {
        const float4 u = ss[0][c4], v = ss2[0][c4];
        atomicAdd(&g_sum[c4 * 4 + 0], u.x); atomicAdd(&g_sumsq[c4 * 4 + 0], v.x);
        atomicAdd(&g_sum[c4 * 4 + 1], u.y); atomicAdd(&g_sumsq[c4 * 4 + 1], v.y);
        atomicAdd(&g_sum[c4 * 4 + 2], u.z); atomicAdd(&g_sumsq[c4 * 4 + 2], v.z);
        atomicAdd(&g_sum[c4 * 4 + 3], u.w); atomicAdd(&g_sumsq[c4 * 4 + 3], v.w);
    }
}

// -------- K6: BatchNorm (biased var) + LeakyReLU -------------------------
// Note: +b before BN cancels exactly in (x - mean), so b is skipped.
__global__ void k_bn(const float* __restrict__ gamma, const float* __restrict__ beta,
                     float* __restrict__ out, int n) {
    const int gid = blockIdx.x * blockDim.x + threadIdx.x;
    if (gid >= n * D4) return;
    const int c4 = gid & 15;
    float4 v  = ((const float4*)g_agg)[gid];
    const float4 sm = ((const float4*)g_sum)[c4];
    const float4 sq = ((const float4*)g_sumsq)[c4];
    const float4 gm = ((const float4*)gamma)[c4];
    const float4 bt = ((const float4*)beta)[c4];
    const float invN = 1.0f / (float)n;

    float m, var, sc, o;
    m = sm.x * invN; var = fmaf(-m, m, sq.x * invN); sc = rsqrtf(var + BN_EPS) * gm.x;
    o = (v.x - m) * sc + bt.x; v.x = (o >= 0.f) ? o : ALPHA * o;
    m = sm.y * invN; var = fmaf(-m, m, sq.y * invN); sc = rsqrtf(var + BN_EPS) * gm.y;
    o = (v.y - m) * sc + bt.y; v.y = (o >= 0.f) ? o : ALPHA * o;
    m = sm.z * invN; var = fmaf(-m, m, sq.z * invN); sc = rsqrtf(var + BN_EPS) * gm.z;
    o = (v.z - m) * sc + bt.z; v.z = (o >= 0.f) ? o : ALPHA * o;
    m = sm.w * invN; var = fmaf(-m, m, sq.w * invN); sc = rsqrtf(var + BN_EPS) * gm.w;
    o = (v.w - m) * sc + bt.w; v.w = (o >= 0.f) ? o : ALPHA * o;

    ((float4*)out)[gid] = v;
}

extern "C" void kernel_launch(void* const* d_in, const int* in_sizes, int n_in,
                              void* d_out, int out_size) {
    const float* x     = (const float*)d_in[0];
    const int*   eidx  = (const int*)d_in[1];
    const float* eattr = (const float*)d_in[2];
    const float* W     = (const float*)d_in[3];
    // d_in[4] = b : cancels in BatchNorm, intentionally unused
    const float* gamma = (const float*)d_in[5];
    const float* beta  = (const float*)d_in[6];
    float* out = (float*)d_out;

    const int N = in_sizes[0] / D;       // 100000
    const int E = in_sizes[2];           // 1200000
    const int* row = eidx;
    const int* col = eidx + E;

    k_init<<<(N + 255) / 256, 256>>>(N);
    k_deg<<<(E + 255) / 256, 256>>>(col, eattr, E);
    k_dis<<<(N + 255) / 256, 256>>>(N);
    k_gemm<<<(N + 15) / 16, dim3(16, 16)>>>(x, W, N);
    {
        long long t = (long long)E * 16;
        k_scatter<<<(unsigned)((t + 255) / 256), 256>>>(row, col, eattr, E);
    }
    k_stats<<<592, 256>>>(N);
    k_bn<<<(N * D4 + 255) / 256, 256>>>(gamma, beta, out, N);
}

// round 2
// speedup vs baseline: 1.0065x; 1.0065x over previous
#include <cuda_runtime.h>

#define NNODES 100000
#define D 64
#define D4 16              // D/4
#define ALPHA 0.01f
#define BN_EPS 1e-5f

// -------- scratch (static device globals; no allocations allowed) --------
__device__ __align__(16) float g_deg[NNODES];
__device__ __align__(16) float g_dis[NNODES];
__device__ __align__(16) float g_h  [(size_t)NNODES * D];
__device__ __align__(16) float g_agg[(size_t)NNODES * D];
__device__ __align__(16) float g_sum[D];
__device__ __align__(16) float g_sumsq[D];

// -------- K0: reset per-replay state (deg=1 for self-loop, stats=0) ------
__global__ void k_init(int n) {
    int i = blockIdx.x * blockDim.x + threadIdx.x;
    if (i < n) g_deg[i] = 1.0f;
    if (i < D) { g_sum[i] = 0.0f; g_sumsq[i] = 0.0f; }
}

// -------- K1: weighted in-degree ----------------------------------------
__global__ void k_deg(const int* __restrict__ col, const float* __restrict__ w, int E) {
    int i = blockIdx.x * blockDim.x + threadIdx.x;
    if (i < E) atomicAdd(&g_deg[col[i]], w[i]);
}

// -------- K2: dis = deg^-1/2 (deg >= 1 always: self-loop weight 1) -------
__global__ void k_dis(int n) {
    int i = blockIdx.x * blockDim.x + threadIdx.x;
    if (i < n) g_dis[i] = rsqrtf(g_deg[i]);
}

// -------- K3: h = x @ W ; agg = h * dis^2 (self-loop contribution) -------
// block = (16,16): 16 nodes per block, each thread -> 4 output cols (float4)
__global__ void k_gemm(const float* __restrict__ x, const float* __restrict__ W, int n) {
    __shared__ float4 Ws[64 * D4];     // W[k][j] as float4 over j
    __shared__ float  xs[16 * 64];     // 16-node x tile
    const int tx = threadIdx.x;        // 0..15 -> col group
    const int ty = threadIdx.y;        // 0..15 -> node in tile
    const int tid = ty * 16 + tx;

    const float4* W4 = (const float4*)W;
#pragma unroll
    for (int i = 0; i < 4; i++) Ws[tid + i * 256] = W4[tid + i * 256];

    const int n0 = blockIdx.x * 16;
    ((float4*)xs)[tid] = ((const float4*)x)[n0 * D4 + tid];
    __syncthreads();

    float4 acc = make_float4(0.f, 0.f, 0.f, 0.f);
#pragma unroll
    for (int k = 0; k < 64; k++) {
        const float  a = xs[ty * 64 + k];
        const float4 w = Ws[k * D4 + tx];
        acc.x = fmaf(a, w.x, acc.x);
        acc.y = fmaf(a, w.y, acc.y);
        acc.z = fmaf(a, w.z, acc.z);
        acc.w = fmaf(a, w.w, acc.w);
    }
    const int node = n0 + ty;
    if (node < n) {
        float s = g_dis[node]; s *= s;           // dis[i]*1*dis[i] = 1/deg
        const int o = node * D4 + tx;
        ((float4*)g_h)[o]   = acc;
        ((float4*)g_agg)[o] = make_float4(acc.x * s, acc.y * s, acc.z * s, acc.w * s);
    }
}

// -------- K4: edge scatter: agg[c] += dis[r]*w*dis[c] * h[r] -------------
// 16 threads per edge, float4 gather + vectorized RED (no return) to L2.
__global__ void k_scatter(const int* __restrict__ row, const int* __restrict__ col,
                          const float* __restrict__ w, int E) {
    const long long gid = (long long)blockIdx.x * blockDim.x + threadIdx.x;
    const int e = (int)(gid >> 4);
    const int l = (int)(gid & 15);
    if (e >= E) return;
    const int r = row[e];
    const int c = col[e];
    const float nm = g_dis[r] * w[e] * g_dis[c];
    const float4 hv = ((const float4*)g_h)[r * D4 + l];
    float4* dst = ((float4*)g_agg) + c * D4 + l;
    asm volatile("red.global.add.v4.f32 [%0], {%1,%2,%3,%4};"
                 :: "l"(dst), "f"(hv.x * nm), "f"(hv.y * nm),
                    "f"(hv.z * nm), "f"(hv.w * nm)
                 : "memory");
}

// -------- K5: per-column sum / sumsq -------------------------------------
// block = 256 threads = 16 row-lanes x 16 col4-groups; grid-stride over rows.
__global__ void k_stats(int n) {
    __shared__ float4 ss [16][16];
    __shared__ float4 ss2[16][16];
    const int tid = threadIdx.x;
    const int c4 = tid & 15;
    const int rl = tid >> 4;
    float4 s  = make_float4(0.f, 0.f, 0.f, 0.f);
    float4 s2 = make_float4(0.f, 0.f, 0.f, 0.f);
    for (int r = blockIdx.x * 16 + rl; r < n; r += gridDim.x * 16) {
        const float4 v = ((const float4*)g_agg)[r * D4 + c4];
        s.x += v.x; s.y += v.y; s.z += v.z; s.w += v.w;
        s2.x = fmaf(v.x, v.x, s2.x);
        s2.y = fmaf(v.y, v.y, s2.y);
        s2.z = fmaf(v.z, v.z, s2.z);
        s2.w = fmaf(v.w, v.w, s2.w);
    }
    ss[rl][c4] = s; ss2[rl][c4] = s2;
    __syncthreads();
#pragma unroll
    for (int off = 8; off > 0; off >>= 1) {
        if (rl < off) {
            float4 a = ss[rl + off][c4], b = ss2[rl + off][c4];
            float4 u = ss[rl][c4],      v = ss2[rl][c4];
            u.x += a.x; u.y += a.y; u.z += a.z; u.w += a.w;
            v.x += b.x; v.y += b.y; v.z += b.z; v.w += b.w;
            ss[rl][c4] = u; ss2[rl][c4] = v;
        }
        __syncthreads();
    }
    if (rl == 0) {
        const float4 u = ss[0][c4], v = ss2[0][c4];
        atomicAdd(&g_sum[c4 * 4 + 0], u.x); atomicAdd(&g_sumsq[c4 * 4 + 0], v.x);
        atomicAdd(&g_sum[c4 * 4 + 1], u.y); atomicAdd(&g_sumsq[c4 * 4 + 1], v.y);
        atomicAdd(&g_sum[c4 * 4 + 2], u.z); atomicAdd(&g_sumsq[c4 * 4 + 2], v.z);
        atomicAdd(&g_sum[c4 * 4 + 3], u.w); atomicAdd(&g_sumsq[c4 * 4 + 3], v.w);
    }
}

// -------- K6: BatchNorm (biased var) + LeakyReLU -------------------------
// Note: +b before BN cancels exactly in (x - mean), so b is skipped.
__global__ void k_bn(const float* __restrict__ gamma, const float* __restrict__ beta,
                     float* __restrict__ out, int n) {
    const int gid = blockIdx.x * blockDim.x + threadIdx.x;
    if (gid >= n * D4) return;
    const int c4 = gid & 15;
    float4 v  = ((const float4*)g_agg)[gid];
    const float4 sm = ((const float4*)g_sum)[c4];
    const float4 sq = ((const float4*)g_sumsq)[c4];
    const float4 gm = ((const float4*)gamma)[c4];
    const float4 bt = ((const float4*)beta)[c4];
    const float invN = 1.0f / (float)n;

    float m, var, sc, o;
    m = sm.x * invN; var = fmaf(-m, m, sq.x * invN); sc = rsqrtf(var + BN_EPS) * gm.x;
    o = (v.x - m) * sc + bt.x; v.x = (o >= 0.f) ? o : ALPHA * o;
    m = sm.y * invN; var = fmaf(-m, m, sq.y * invN); sc = rsqrtf(var + BN_EPS) * gm.y;
    o = (v.y - m) * sc + bt.y; v.y = (o >= 0.f) ? o : ALPHA * o;
    m = sm.z * invN; var = fmaf(-m, m, sq.z * invN); sc = rsqrtf(var + BN_EPS) * gm.z;
    o = (v.z - m) * sc + bt.z; v.z = (o >= 0.f) ? o : ALPHA * o;
    m = sm.w * invN; var = fmaf(-m, m, sq.w * invN); sc = rsqrtf(var + BN_EPS) * gm.w;
    o = (v.w - m) * sc + bt.w; v.w = (o >= 0.f) ? o : ALPHA * o;

    ((float4*)out)[gid] = v;
}

extern "C" void kernel_launch(void* const* d_in, const int* in_sizes, int n_in,
                              void* d_out, int out_size) {
    const float* x     = (const float*)d_in[0];
    const int*   eidx  = (const int*)d_in[1];
    const float* eattr = (const float*)d_in[2];
    const float* W     = (const float*)d_in[3];
    // d_in[4] = b : cancels in BatchNorm, intentionally unused
    const float* gamma = (const float*)d_in[5];
    const float* beta  = (const float*)d_in[6];
    float* out = (float*)d_out;

    const int N = in_sizes[0] / D;       // 100000
    const int E = in_sizes[2];           // 1200000
    const int* row = eidx;
    const int* col = eidx + E;

    k_init<<<(N + 255) / 256, 256>>>(N);
    k_deg<<<(E + 255) / 256, 256>>>(col, eattr, E);
    k_dis<<<(N + 255) / 256, 256>>>(N);
    k_gemm<<<(N + 15) / 16, dim3(16, 16)>>>(x, W, N);
    {
        long long t = (long long)E * 16;
        k_scatter<<<(unsigned)((t + 255) / 256), 256>>>(row, col, eattr, E);
    }
    k_stats<<<592, 256>>>(N);
    k_bn<<<(N * D4 + 255) / 256, 256>>>(gamma, beta, out, N);
}

// round 3
// speedup vs baseline: 1.2496x; 1.2416x over previous
#include <cuda_runtime.h>

#define NNODES 100000
#define D 64
#define D4 16              // D/4
#define MT 128             // nodes per GEMM block
#define ALPHA 0.01f
#define BN_EPS 1e-5f

// -------- scratch (static device globals; no allocations allowed) --------
__device__ __align__(16) float g_deg[NNODES];
__device__ __align__(16) float g_dis[NNODES];
__device__ __align__(16) float g_h  [(size_t)NNODES * D];
__device__ __align__(16) float g_agg[(size_t)NNODES * D];
__device__ __align__(16) float g_sum[D];
__device__ __align__(16) float g_sumsq[D];

// -------- K0: reset per-replay state (deg=1 for self-loop, stats=0) ------
__global__ void k_init(int n) {
    int i = blockIdx.x * blockDim.x + threadIdx.x;
    if (i < n) g_deg[i] = 1.0f;
    if (i < D) { g_sum[i] = 0.0f; g_sumsq[i] = 0.0f; }
}

// -------- K1: weighted in-degree ----------------------------------------
__global__ void k_deg(const int* __restrict__ col, const float* __restrict__ w, int E) {
    int i = blockIdx.x * blockDim.x + threadIdx.x;
    if (i < E) atomicAdd(&g_deg[col[i]], w[i]);
}

// -------- K2: dis = deg^-1/2 (deg >= 1 always: self-loop weight 1) -------
__global__ void k_dis(int n) {
    int i = blockIdx.x * blockDim.x + threadIdx.x;
    if (i < n) g_dis[i] = rsqrtf(g_deg[i]);
}

// -------- K3: h = x @ W ; agg = h/deg (self-loop term) --------------------
// 128 nodes/block, 256 threads. Thread (tx,ty) computes 8 nodes x 4 cols.
// x tile kept ROW-MAJOR in smem: inner-loop x reads are same-address
// broadcasts across the 16 tx lanes -> 1 crossbar phase, no conflicts.
__global__ void __launch_bounds__(256) k_gemm(const float* __restrict__ x,
                                              const float* __restrict__ W, int n) {
    __shared__ float  xs[MT * 64];        // 32 KB, row-major [m][k]
    __shared__ float4 Ws[64 * D4];        // 16 KB, W[k][j] as float4 over j

    const int tid = threadIdx.x;
    const int tx = tid & 15;              // col4 group
    const int ty = tid >> 4;              // node group (8 nodes each)

    const float4* W4 = (const float4*)W;
#pragma unroll
    for (int i = 0; i < 4; i++) Ws[tid + i * 256] = W4[tid + i * 256];

    const int m0 = blockIdx.x * MT;
#pragma unroll
    for (int t = 0; t < 8; t++) {         // 128*16 float4 / 256 threads = 8 each
        const int idx = tid + t * 256;
        const int node = m0 + (idx >> 4);
        float4 v = make_float4(0.f, 0.f, 0.f, 0.f);
        if (node < n) v = ((const float4*)x)[node * D4 + (idx & 15)];
        ((float4*)xs)[idx] = v;
    }
    __syncthreads();

    float4 acc[8];
#pragma unroll
    for (int i = 0; i < 8; i++) acc[i] = make_float4(0.f, 0.f, 0.f, 0.f);

    const float* xrow = xs + (ty * 8) * 64;
#pragma unroll 8
    for (int k = 0; k < 64; k++) {
        const float4 w = Ws[k * D4 + tx];
#pragma unroll
        for (int i = 0; i < 8; i++) {
            const float a = xrow[i * 64 + k];   // broadcast across tx lanes
            acc[i].x = fmaf(a, w.x, acc[i].x);
            acc[i].y = fmaf(a, w.y, acc[i].y);
            acc[i].z = fmaf(a, w.z, acc[i].z);
            acc[i].w = fmaf(a, w.w, acc[i].w);
        }
    }

#pragma unroll
    for (int i = 0; i < 8; i++) {
        const int node = m0 + ty * 8 + i;
        if (node < n) {
            float s = g_dis[node]; s *= s;      // dis[i]*1*dis[i] = 1/deg
            const int o = node * D4 + tx;
            ((float4*)g_h)[o]   = acc[i];
            ((float4*)g_agg)[o] = make_float4(acc[i].x * s, acc[i].y * s,
                                              acc[i].z * s, acc[i].w * s);
        }
    }
}

// -------- K4: edge scatter: agg[c] += dis[r]*w*dis[c] * h[r] -------------
// 16 threads per edge, float4 gather + vectorized RED (no return) to L2.
__global__ void k_scatter(const int* __restrict__ row, const int* __restrict__ col,
                          const float* __restrict__ w, int E) {
    const long long gid = (long long)blockIdx.x * blockDim.x + threadIdx.x;
    const int e = (int)(gid >> 4);
    const int l = (int)(gid & 15);
    if (e >= E) return;
    const int r = row[e];
    const int c = col[e];
    const float nm = g_dis[r] * w[e] * g_dis[c];
    const float4 hv = ((const float4*)g_h)[r * D4 + l];
    float4* dst = ((float4*)g_agg) + c * D4 + l;
    asm volatile("red.global.add.v4.f32 [%0], {%1,%2,%3,%4};"
                 :: "l"(dst), "f"(hv.x * nm), "f"(hv.y * nm),
                    "f"(hv.z * nm), "f"(hv.w * nm)
                 : "memory");
}

// -------- K5: per-column sum / sumsq -------------------------------------
__global__ void k_stats(int n) {
    __shared__ float4 ss [16][16];
    __shared__ float4 ss2[16][16];
    const int tid = threadIdx.x;
    const int c4 = tid & 15;
    const int rl = tid >> 4;
    float4 s  = make_float4(0.f, 0.f, 0.f, 0.f);
    float4 s2 = make_float4(0.f, 0.f, 0.f, 0.f);
    for (int r = blockIdx.x * 16 + rl; r < n; r += gridDim.x * 16) {
        const float4 v = ((const float4*)g_agg)[r * D4 + c4];
        s.x += v.x; s.y += v.y; s.z += v.z; s.w += v.w;
        s2.x = fmaf(v.x, v.x, s2.x);
        s2.y = fmaf(v.y, v.y, s2.y);
        s2.z = fmaf(v.z, v.z, s2.z);
        s2.w = fmaf(v.w, v.w, s2.w);
    }
    ss[rl][c4] = s; ss2[rl][c4] = s2;
    __syncthreads();
#pragma unroll
    for (int off = 8; off > 0; off >>= 1) {
        if (rl < off) {
            float4 a = ss[rl + off][c4], b = ss2[rl + off][c4];
            float4 u = ss[rl][c4],      v = ss2[rl][c4];
            u.x += a.x; u.y += a.y; u.z += a.z; u.w += a.w;
            v.x += b.x; v.y += b.y; v.z += b.z; v.w += b.w;
            ss[rl][c4] = u; ss2[rl][c4] = v;
        }
        __syncthreads();
    }
    if (rl == 0) {
        const float4 u = ss[0][c4], v = ss2[0][c4];
        atomicAdd(&g_sum[c4 * 4 + 0], u.x); atomicAdd(&g_sumsq[c4 * 4 + 0], v.x);
        atomicAdd(&g_sum[c4 * 4 + 1], u.y); atomicAdd(&g_sumsq[c4 * 4 + 1], v.y);
        atomicAdd(&g_sum[c4 * 4 + 2], u.z); atomicAdd(&g_sumsq[c4 * 4 + 2], v.z);
        atomicAdd(&g_sum[c4 * 4 + 3], u.w); atomicAdd(&g_sumsq[c4 * 4 + 3], v.w);
    }
}

// -------- K6: BatchNorm (biased var) + LeakyReLU -------------------------
// Note: +b before BN cancels exactly in (x - mean), so b is skipped.
__global__ void k_bn(const float* __restrict__ gamma, const float* __restrict__ beta,
                     float* __restrict__ out, int n) {
    const int gid = blockIdx.x * blockDim.x + threadIdx.x;
    if (gid >= n * D4) return;
    const int c4 = gid & 15;
    float4 v  = ((const float4*)g_agg)[gid];
    const float4 sm = ((const float4*)g_sum)[c4];
    const float4 sq = ((const float4*)g_sumsq)[c4];
    const float4 gm = ((const float4*)gamma)[c4];
    const float4 bt = ((const float4*)beta)[c4];
    const float invN = 1.0f / (float)n;

    float m, var, sc, o;
    m = sm.x * invN; var = fmaf(-m, m, sq.x * invN); sc = rsqrtf(var + BN_EPS) * gm.x;
    o = (v.x - m) * sc + bt.x; v.x = (o >= 0.f) ? o : ALPHA * o;
    m = sm.y * invN; var = fmaf(-m, m, sq.y * invN); sc = rsqrtf(var + BN_EPS) * gm.y;
    o = (v.y - m) * sc + bt.y; v.y = (o >= 0.f) ? o : ALPHA * o;
    m = sm.z * invN; var = fmaf(-m, m, sq.z * invN); sc = rsqrtf(var + BN_EPS) * gm.z;
    o = (v.z - m) * sc + bt.z; v.z = (o >= 0.f) ? o : ALPHA * o;
    m = sm.w * invN; var = fmaf(-m, m, sq.w * invN); sc = rsqrtf(var + BN_EPS) * gm.w;
    o = (v.w - m) * sc + bt.w; v.w = (o >= 0.f) ? o : ALPHA * o;

    ((float4*)out)[gid] = v;
}

extern "C" void kernel_launch(void* const* d_in, const int* in_sizes, int n_in,
                              void* d_out, int out_size) {
    const float* x     = (const float*)d_in[0];
    const int*   eidx  = (const int*)d_in[1];
    const float* eattr = (const float*)d_in[2];
    const float* W     = (const float*)d_in[3];
    // d_in[4] = b : cancels in BatchNorm, intentionally unused
    const float* gamma = (const float*)d_in[5];
    const float* beta  = (const float*)d_in[6];
    float* out = (float*)d_out;

    const int N = in_sizes[0] / D;       // 100000
    const int E = in_sizes[2];           // 1200000
    const int* row = eidx;
    const int* col = eidx + E;

    k_init<<<(N + 255) / 256, 256>>>(N);
    k_deg<<<(E + 255) / 256, 256>>>(col, eattr, E);
    k_dis<<<(N + 255) / 256, 256>>>(N);
    k_gemm<<<(N + MT - 1) / MT, 256>>>(x, W, N);
    {
        long long t = (long long)E * 16;
        k_scatter<<<(unsigned)((t + 255) / 256), 256>>>(row, col, eattr, E);
    }
    k_stats<<<592, 256>>>(N);
    k_bn<<<(N * D4 + 255) / 256, 256>>>(gamma, beta, out, N);
}